// round 12
// baseline (speedup 1.0000x reference)
#include <cuda_runtime.h>
#include <cstdint>

#define TBK   64
#define NTH   256
#define HID   128
#define NEXP  64
#define XST   136       // xs row stride (fp32 words)
#define WST   68        // Wt row stride (u32 pairs)
#define LST   68        // logits row stride (fp32 words)
#define NEGINF (__int_as_float(0xff800000u))

// ---- smem word offsets ----
#define SW_XS    0                    // fp32 [64][136]  (overlay: L [64][68] after GEMM)
#define SW_WT    8704                 // u32  3 x [64][68] bf16-pair terms
#define SW_ZINV  21760                // fp32 [64]
#define SW_CNT   21824                // int  [64]
#define SW_LASTF 21888                // int
#define SW_RS    21892                // fp32 [2][64] recompute scratch
#define SW_TOTAL 22020
#define SW_PART  8704                 // overlay on Wt0: fp32 [4][64]
#define SW_DTERM 13056                // overlay on Wt1: double[64]

__device__ unsigned long long g_scoreFix[NEXP];
__device__ int g_cnt[NEXP];
__device__ int g_sync;

// pack two fp32 -> bf16x2 {lo, hi}; PTX cvt packs first src into HIGH half
__device__ __forceinline__ uint32_t f2bf2(float lo, float hi) {
    uint32_t r;
    asm("cvt.rn.bf16x2.f32 %0, %1, %2;" : "=r"(r) : "f"(hi), "f"(lo));
    return r;
}
__device__ __forceinline__ float bflo(uint32_t p) { return __uint_as_float(p << 16); }
__device__ __forceinline__ float bfhi(uint32_t p) { return __uint_as_float(p & 0xFFFF0000u); }

// C-in chained accumulate (for small correction terms)
__device__ __forceinline__ void mma16816(float* d, const uint32_t* a, uint32_t b0, uint32_t b1) {
    asm volatile(
        "mma.sync.aligned.m16n8k16.row.col.f32.bf16.bf16.f32 "
        "{%0,%1,%2,%3}, {%4,%5,%6,%7}, {%8,%9}, {%0,%1,%2,%3};"
        : "+f"(d[0]), "+f"(d[1]), "+f"(d[2]), "+f"(d[3])
        : "r"(a[0]), "r"(a[1]), "r"(a[2]), "r"(a[3]), "r"(b0), "r"(b1));
}
// zero-C MMA: D = A*B (internal truncation stays at partial magnitude,
// no cross-MMA compounding at full logit magnitude)
__device__ __forceinline__ void mma_zc(float* d, const uint32_t* a, uint32_t b0, uint32_t b1) {
    asm volatile(
        "mma.sync.aligned.m16n8k16.row.col.f32.bf16.bf16.f32 "
        "{%0,%1,%2,%3}, {%4,%5,%6,%7}, {%8,%9}, {%10,%10,%10,%10};"
        : "=f"(d[0]), "=f"(d[1]), "=f"(d[2]), "=f"(d[3])
        : "r"(a[0]), "r"(a[1]), "r"(a[2]), "r"(a[3]), "r"(b0), "r"(b1), "f"(0.f));
}

// one masked argmax pass over 64 register floats; exact lower-index tie-break
__device__ __forceinline__ int find_top(const float (&v)[64], unsigned long long mask, float& mval) {
    float w[32];
#pragma unroll
    for (int i = 0; i < 32; ++i) {
        float x0 = ((mask >> (2 * i)) & 1ull)     ? NEGINF : v[2 * i];
        float x1 = ((mask >> (2 * i + 1)) & 1ull) ? NEGINF : v[2 * i + 1];
        w[i] = fmaxf(x0, x1);
    }
#pragma unroll
    for (int n = 16; n >= 1; n >>= 1)
#pragma unroll
        for (int i = 0; i < n; ++i) w[i] = fmaxf(w[2 * i], w[2 * i + 1]);
    float m = w[0];
    int b0 = 64, b1 = 64, b2 = 64, b3 = 64;
#pragma unroll
    for (int i = 15; i >= 0; --i) {
        float y0 = ((mask >> i) & 1ull) ? NEGINF : v[i];
        b0 = (y0 == m) ? i : b0;
        float y1 = ((mask >> (i + 16)) & 1ull) ? NEGINF : v[i + 16];
        b1 = (y1 == m) ? (i + 16) : b1;
        float y2 = ((mask >> (i + 32)) & 1ull) ? NEGINF : v[i + 32];
        b2 = (y2 == m) ? (i + 32) : b2;
        float y3 = ((mask >> (i + 48)) & 1ull) ? NEGINF : v[i + 48];
        b3 = (y3 == m) ? (i + 48) : b3;
    }
    mval = m;
    return (b0 < 64) ? b0 : ((b1 < 64) ? b1 : ((b2 < 64) ? b2 : b3));
}

extern __shared__ float smf[];

__global__ __launch_bounds__(NTH, 2)
void moe_main(const float* __restrict__ x, const float* __restrict__ W,
              float* __restrict__ out, int N) {
    const int tid  = threadIdx.x;
    const int wid  = tid >> 5;
    const int lane = tid & 31;
    const long long blk = blockIdx.x;

    float*    xs   = smf + SW_XS;
    uint32_t* Wt   = reinterpret_cast<uint32_t*>(smf + SW_WT);
    float*    zinv = smf + SW_ZINV;
    int*      cntS = reinterpret_cast<int*>(smf + SW_CNT);
    int*      lastF = reinterpret_cast<int*>(smf + SW_LASTF);
    float*    rescr = smf + SW_RS;
    float*    L    = smf + SW_XS;       // overlay after GEMM
    float*    part = smf + SW_PART;     // overlay on Wt0
    double*   dterm = reinterpret_cast<double*>(smf + SW_DTERM);

    // ---- stage x (fp32, coalesced LDG.128, contiguous STS.128) ----
    {
        const float4* gx = reinterpret_cast<const float4*>(x + blk * (long long)(TBK * HID));
#pragma unroll
        for (int c = 0; c < 8; ++c) {
            int f = c * NTH + tid;             // float4 index over [64][32]
            float4 g = gx[f];
            int t  = f >> 5;
            int k4 = (f & 31) * 4;
            *reinterpret_cast<float4*>(xs + t * XST + k4) = g;
        }
    }

    // ---- stage W: 3 bf16-pair terms (thread: e=tid>>2, 32 k vals) ----
    {
        int e  = tid >> 2;
        int kq = (tid & 3) * 32;
        float wv[32];
        const float4* gw = reinterpret_cast<const float4*>(W + e * HID + kq);
#pragma unroll
        for (int j = 0; j < 8; ++j) {
            float4 g = gw[j];
            wv[4 * j] = g.x; wv[4 * j + 1] = g.y; wv[4 * j + 2] = g.z; wv[4 * j + 3] = g.w;
        }
#pragma unroll
        for (int term = 0; term < 3; ++term) {
            uint32_t pk[16];
#pragma unroll
            for (int j = 0; j < 16; ++j) {
                pk[j] = f2bf2(wv[2 * j], wv[2 * j + 1]);
                wv[2 * j]     -= bflo(pk[j]);
                wv[2 * j + 1] -= bfhi(pk[j]);
            }
            uint32_t* dst = Wt + term * (NEXP * WST) + e * WST + (tid & 3) * 16;
#pragma unroll
            for (int u = 0; u < 4; ++u)
                *reinterpret_cast<uint4*>(dst + 4 * u) =
                    make_uint4(pk[4 * u], pk[4 * u + 1], pk[4 * u + 2], pk[4 * u + 3]);
        }
    }
    if (tid < NEXP) cntS[tid] = 0;
    __syncthreads();

    // ---- GEMM: 8 warps = 4(m16) x 2(n32) ----
    const int g  = lane >> 2;
    const int tg = lane & 3;
    const int m0 = (wid & 3) * 16;
    const int n0 = (wid >> 2) * 32;

    float accM[4][4], accC[4][4];
#pragma unroll
    for (int t = 0; t < 4; ++t)
#pragma unroll
        for (int i = 0; i < 4; ++i) { accM[t][i] = 0.f; accC[t][i] = 0.f; }

    const float* xr0 = xs + (m0 + g) * XST + tg * 2;
    const float* xr1 = xs + (m0 + g + 8) * XST + tg * 2;

#pragma unroll
    for (int s = 0; s < 8; ++s) {
        const int c = 16 * s;
        float2 x00 = *reinterpret_cast<const float2*>(xr0 + c);
        float2 x01 = *reinterpret_cast<const float2*>(xr0 + c + 8);
        float2 x10 = *reinterpret_cast<const float2*>(xr1 + c);
        float2 x11 = *reinterpret_cast<const float2*>(xr1 + c + 8);

        uint32_t A[3][4];
#pragma unroll
        for (int term = 0; term < 3; ++term) {
            A[term][0] = f2bf2(x00.x, x00.y);
            A[term][1] = f2bf2(x10.x, x10.y);
            A[term][2] = f2bf2(x01.x, x01.y);
            A[term][3] = f2bf2(x11.x, x11.y);
            if (term < 2) {
                x00.x -= bflo(A[term][0]); x00.y -= bfhi(A[term][0]);
                x10.x -= bflo(A[term][1]); x10.y -= bfhi(A[term][1]);
                x01.x -= bflo(A[term][2]); x01.y -= bfhi(A[term][2]);
                x11.x -= bflo(A[term][3]); x11.y -= bfhi(A[term][3]);
            }
        }

        const int bp = 8 * s + tg;
        uint32_t B[3][4][2];
#pragma unroll
        for (int t = 0; t < 4; ++t) {
            int row = (n0 + 8 * t + g) * WST;
#pragma unroll
            for (int term = 0; term < 3; ++term) {
                B[term][t][0] = Wt[term * (NEXP * WST) + row + bp];
                B[term][t][1] = Wt[term * (NEXP * WST) + row + bp + 4];
            }
        }

        // main product: zero-C MMA, fold with scalar FADD (RN)
#pragma unroll
        for (int t = 0; t < 4; ++t) {
            float tmp[4];
            mma_zc(tmp, A[0], B[0][t][0], B[0][t][1]);
            accM[t][0] += tmp[0]; accM[t][1] += tmp[1];
            accM[t][2] += tmp[2]; accM[t][3] += tmp[3];
        }
        // corrections (i+j in 1..3) -> accC (C-in chaining fine at small magnitude)
#pragma unroll
        for (int t = 0; t < 4; ++t) mma16816(accC[t], A[0], B[1][t][0], B[1][t][1]);
#pragma unroll
        for (int t = 0; t < 4; ++t) mma16816(accC[t], A[1], B[0][t][0], B[0][t][1]);
#pragma unroll
        for (int t = 0; t < 4; ++t) mma16816(accC[t], A[0], B[2][t][0], B[2][t][1]);
#pragma unroll
        for (int t = 0; t < 4; ++t) mma16816(accC[t], A[1], B[1][t][0], B[1][t][1]);
#pragma unroll
        for (int t = 0; t < 4; ++t) mma16816(accC[t], A[2], B[0][t][0], B[0][t][1]);
#pragma unroll
        for (int t = 0; t < 4; ++t) mma16816(accC[t], A[1], B[2][t][0], B[2][t][1]);
#pragma unroll
        for (int t = 0; t < 4; ++t) mma16816(accC[t], A[2], B[1][t][0], B[1][t][1]);
    }
    __syncthreads();   // all xs/Wt reads done; safe to overlay L

    // ---- scatter logits (accM + accC) to L[token][expert] ----
#pragma unroll
    for (int t = 0; t < 4; ++t) {
        int col = n0 + 8 * t + tg * 2;
        *reinterpret_cast<float2*>(L + (m0 + g) * LST + col) =
            make_float2(accM[t][0] + accC[t][0], accM[t][1] + accC[t][1]);
        *reinterpret_cast<float2*>(L + (m0 + g + 8) * LST + col) =
            make_float2(accM[t][2] + accC[t][2], accM[t][3] + accC[t][3]);
    }
    __syncthreads();

    // ---- per-token top-6 / softmax / outputs (threads 0..63 = warps 0,1) ----
    if (tid < TBK) {
        const int t = tid;
        const int lw = tid & 31;
        const int wE = tid >> 5;
        float v[64];
#pragma unroll
        for (int j = 0; j < 16; ++j) {
            float4 q = *reinterpret_cast<const float4*>(L + t * LST + 4 * j);
            v[4 * j] = q.x; v[4 * j + 1] = q.y; v[4 * j + 2] = q.z; v[4 * j + 3] = q.w;
        }

        // top-7 to measure boundary gaps
        unsigned long long mask = 0ull;
        float tv[7]; int ti[7];
#pragma unroll
        for (int p = 0; p < 7; ++p) {
            ti[p] = find_top(v, mask, tv[p]);
            mask |= 1ull << ti[p];
        }
        bool flg = false;
#pragma unroll
        for (int p = 0; p < 6; ++p) flg |= (tv[p] - tv[p + 1]) < 1e-5f;

        // near-tie tokens: warp-cooperative exact fp32 recompute (rare ~1e-3)
        unsigned fmsk = __ballot_sync(0xffffffffu, flg);
        float* rs = rescr + wE * 64;
        while (fmsk) {
            int src = __ffs(fmsk) - 1;
            fmsk &= fmsk - 1;
            long long gtok = blk * TBK + wE * 32 + src;
            const float* xrow = x + gtok * HID;
            const float* w0 = W + (2 * lw) * HID;
            float a0 = 0.f, a1 = 0.f;
#pragma unroll 8
            for (int k = 0; k < HID; ++k) {
                float xv = __ldg(xrow + k);
                a0 = fmaf(xv, __ldg(w0 + k), a0);
                a1 = fmaf(xv, __ldg(w0 + HID + k), a1);
            }
            rs[2 * lw] = a0;
            rs[2 * lw + 1] = a1;
            __syncwarp();
            if (lw == src) {
#pragma unroll
                for (int i = 0; i < 64; ++i) v[i] = rs[i];
            }
            __syncwarp();
        }
        if (flg) {   // redo selection on exact logits
            mask = 0ull;
#pragma unroll
            for (int p = 0; p < 6; ++p) {
                ti[p] = find_top(v, mask, tv[p]);
                mask |= 1ull << ti[p];
            }
        }

        float m1 = tv[0];
        float Z = 0.f;
#pragma unroll
        for (int j = 0; j < 16; ++j) {
            float e0 = __expf(v[4 * j]     - m1);
            float e1 = __expf(v[4 * j + 1] - m1);
            float e2 = __expf(v[4 * j + 2] - m1);
            float e3 = __expf(v[4 * j + 3] - m1);
            Z += (e0 + e1) + (e2 + e3);
            *reinterpret_cast<float4*>(L + t * LST + 4 * j) = make_float4(e0, e1, e2, e3);
        }
        zinv[t] = 1.f / Z;

        float ev[6]; float E6 = 0.f;
#pragma unroll
        for (int p = 0; p < 6; ++p) { ev[p] = __expf(tv[p] - m1); E6 += ev[p]; }
        float invd = 1.f / (E6 + 1e-20f * Z);   // == ref renormalization exactly

        size_t gt = (size_t)blk * TBK + t;
        float* oi = out + gt * 6;
        float* ow = out + (size_t)N * 6 + gt * 6;
#pragma unroll
        for (int p = 0; p < 6; ++p) {
            oi[p] = (float)ti[p];
            ow[p] = ev[p] * invd;
            atomicAdd(&cntS[ti[p]], 1);
        }
    }
    __syncthreads();

    // ---- Pi column sums (part overlays Wt0 — Wt reads finished) ----
    {
        int e = tid & 63;
        int q = tid >> 6;
        float s0 = 0.f, s1 = 0.f;
#pragma unroll
        for (int j = 0; j < 16; j += 2) {
            int t0 = q * 16 + j;
            s0 = fmaf(L[(t0 + 0) * LST + e], zinv[t0 + 0], s0);
            s1 = fmaf(L[(t0 + 1) * LST + e], zinv[t0 + 1], s1);
        }
        part[q * 64 + e] = s0 + s1;
    }
    __syncthreads();

    if (tid < NEXP) {
        float s = ((part[tid] + part[64 + tid]) + (part[128 + tid] + part[192 + tid]));
        atomicAdd(&g_scoreFix[tid], (unsigned long long)(s * 1073741824.0f)); // *2^30
        atomicAdd(&g_cnt[tid], cntS[tid]);
    }
    __syncthreads();

    // ---- last-block finalize: aux loss + accumulator self-reset ----
    if (tid == 0) {
        __threadfence();
        int r = atomicAdd(&g_sync, 1);
        lastF[0] = (r == (int)gridDim.x - 1) ? 1 : 0;
    }
    __syncthreads();
    if (lastF[0]) {
        __threadfence();
        if (tid < NEXP) {
            double invN = 1.0 / (double)N;
            double Pi = (double)g_scoreFix[tid] * (1.0 / 1073741824.0) * invN;
            double fi = (double)g_cnt[tid] * 64.0 / ((double)N * 6.0);
            dterm[tid] = Pi * fi;
            g_scoreFix[tid] = 0ull;
            g_cnt[tid]      = 0;
        }
        __syncthreads();
        if (tid == 0) {
            double aux = 0.0;
            for (int e = 0; e < NEXP; ++e) aux += dterm[e];
            out[(size_t)N * 12] = (float)(aux * 1e-3);
            g_sync = 0;
        }
    }
}

extern "C" void kernel_launch(void* const* d_in, const int* in_sizes, int n_in,
                              void* d_out, int out_size) {
    const float* x = (const float*)d_in[0];
    const float* W = (const float*)d_in[1];
    int N = in_sizes[0] / HID;

    int smem_bytes = SW_TOTAL * (int)sizeof(float) + 128;
    cudaFuncSetAttribute(moe_main, cudaFuncAttributeMaxDynamicSharedMemorySize, smem_bytes);
    moe_main<<<N / TBK, NTH, smem_bytes>>>(x, W, (float*)d_out, N);
}

// round 13
// speedup vs baseline: 1.3674x; 1.3674x over previous
#include <cuda_runtime.h>
#include <cstdint>

#define TBK   128
#define NTH   256
#define HID   128
#define NEXP  64
#define XST   132       // xs row stride (fp32 words)
#define WST   68        // Wt row stride (u32 words)
#define LST   68        // logits row stride (fp32 words)
#define NEGINF (__int_as_float(0xff800000u))

// ---- smem word offsets ----
#define SW_XS    0                    // fp32 [128][132] (overlay: L [128][68] after GEMM)
#define SW_WT    16896                // u32  2 x [64][68] bf16-pair terms
#define SW_ZINV  25600                // fp32 [128]
#define SW_CNT   25728                // int  [64]
#define SW_LASTF 25792                // int
#define SW_RS    25796                // fp32 [4][64] recompute scratch
#define SW_TOTAL 26052
#define SW_PART  16896                // overlay on Wt: fp32 [4][64]
#define SW_DTERM 17408                // overlay on Wt: double[64] (byte 69632, 8-aligned)

__device__ unsigned long long g_scoreFix[NEXP];
__device__ int g_cnt[NEXP];
__device__ int g_sync;

// pack two fp32 -> bf16x2 {lo, hi}; PTX cvt packs first src into HIGH half
__device__ __forceinline__ uint32_t f2bf2(float lo, float hi) {
    uint32_t r;
    asm("cvt.rn.bf16x2.f32 %0, %1, %2;" : "=r"(r) : "f"(hi), "f"(lo));
    return r;
}
__device__ __forceinline__ float bflo(uint32_t p) { return __uint_as_float(p << 16); }
__device__ __forceinline__ float bfhi(uint32_t p) { return __uint_as_float(p & 0xFFFF0000u); }

__device__ __forceinline__ uint32_t smem_u32(const void* p) {
    uint32_t a;
    asm("{ .reg .u64 t; cvta.to.shared.u64 t, %1; cvt.u32.u64 %0, t; }" : "=r"(a) : "l"(p));
    return a;
}
__device__ __forceinline__ void cpasync16(uint32_t dst, const void* src) {
    asm volatile("cp.async.cg.shared.global [%0], [%1], 16;" :: "r"(dst), "l"(src) : "memory");
}

// C-in chained accumulate (small corrections only)
__device__ __forceinline__ void mma16816(float* d, const uint32_t* a, uint32_t b0, uint32_t b1) {
    asm volatile(
        "mma.sync.aligned.m16n8k16.row.col.f32.bf16.bf16.f32 "
        "{%0,%1,%2,%3}, {%4,%5,%6,%7}, {%8,%9}, {%0,%1,%2,%3};"
        : "+f"(d[0]), "+f"(d[1]), "+f"(d[2]), "+f"(d[3])
        : "r"(a[0]), "r"(a[1]), "r"(a[2]), "r"(a[3]), "r"(b0), "r"(b1));
}
// zero-C MMA: no cross-MMA truncation compounding at logit magnitude
__device__ __forceinline__ void mma_zc(float* d, const uint32_t* a, uint32_t b0, uint32_t b1) {
    asm volatile(
        "mma.sync.aligned.m16n8k16.row.col.f32.bf16.bf16.f32 "
        "{%0,%1,%2,%3}, {%4,%5,%6,%7}, {%8,%9}, {%10,%10,%10,%10};"
        : "=f"(d[0]), "=f"(d[1]), "=f"(d[2]), "=f"(d[3])
        : "r"(a[0]), "r"(a[1]), "r"(a[2]), "r"(a[3]), "r"(b0), "r"(b1), "f"(0.f));
}

// one masked argmax pass over 64 register floats; exact lower-index tie-break
__device__ __forceinline__ int find_top(const float (&v)[64], unsigned long long mask, float& mval) {
    float w[32];
#pragma unroll
    for (int i = 0; i < 32; ++i) {
        float x0 = ((mask >> (2 * i)) & 1ull)     ? NEGINF : v[2 * i];
        float x1 = ((mask >> (2 * i + 1)) & 1ull) ? NEGINF : v[2 * i + 1];
        w[i] = fmaxf(x0, x1);
    }
#pragma unroll
    for (int n = 16; n >= 1; n >>= 1)
#pragma unroll
        for (int i = 0; i < n; ++i) w[i] = fmaxf(w[2 * i], w[2 * i + 1]);
    float m = w[0];
    int b0 = 64, b1 = 64, b2 = 64, b3 = 64;
#pragma unroll
    for (int i = 15; i >= 0; --i) {
        float y0 = ((mask >> i) & 1ull) ? NEGINF : v[i];
        b0 = (y0 == m) ? i : b0;
        float y1 = ((mask >> (i + 16)) & 1ull) ? NEGINF : v[i + 16];
        b1 = (y1 == m) ? (i + 16) : b1;
        float y2 = ((mask >> (i + 32)) & 1ull) ? NEGINF : v[i + 32];
        b2 = (y2 == m) ? (i + 32) : b2;
        float y3 = ((mask >> (i + 48)) & 1ull) ? NEGINF : v[i + 48];
        b3 = (y3 == m) ? (i + 48) : b3;
    }
    mval = m;
    return (b0 < 64) ? b0 : ((b1 < 64) ? b1 : ((b2 < 64) ? b2 : b3));
}

extern __shared__ float smf[];

__global__ __launch_bounds__(NTH, 2)
void moe_main(const float* __restrict__ x, const float* __restrict__ W,
              float* __restrict__ out, int N) {
    const int tid  = threadIdx.x;
    const int wid  = tid >> 5;
    const int lane = tid & 31;
    const long long blk = blockIdx.x;

    float*    xs    = smf + SW_XS;
    uint32_t* Wt    = reinterpret_cast<uint32_t*>(smf + SW_WT);
    float*    zinv  = smf + SW_ZINV;
    int*      cntS  = reinterpret_cast<int*>(smf + SW_CNT);
    int*      lastF = reinterpret_cast<int*>(smf + SW_LASTF);
    float*    rescr = smf + SW_RS;
    float*    L     = smf + SW_XS;       // overlay after GEMM
    float*    part  = smf + SW_PART;     // overlay on Wt
    double*   dterm = reinterpret_cast<double*>(smf + SW_DTERM);
    const uint32_t sbase = smem_u32(smf);

    // ---- x tile via cp.async (overlaps with W split below) ----
    {
        const float4* gx = reinterpret_cast<const float4*>(x + blk * (long long)(TBK * HID));
#pragma unroll
        for (int c = 0; c < 16; ++c) {
            int f = c * NTH + tid;             // float4 index over [128][32]
            int t  = f >> 5;
            int k4 = (f & 31) * 4;
            cpasync16(sbase + (uint32_t)(t * XST + k4) * 4u, gx + f);
        }
        asm volatile("cp.async.commit_group;" ::: "memory");
    }

    // ---- stage W: 2 bf16-pair terms (thread: e=tid>>2, 32 k vals) ----
    {
        int e  = tid >> 2;
        int kq = (tid & 3) * 32;
        float wv[32];
        const float4* gw = reinterpret_cast<const float4*>(W + e * HID + kq);
#pragma unroll
        for (int j = 0; j < 8; ++j) {
            float4 g = gw[j];
            wv[4 * j] = g.x; wv[4 * j + 1] = g.y; wv[4 * j + 2] = g.z; wv[4 * j + 3] = g.w;
        }
#pragma unroll
        for (int term = 0; term < 2; ++term) {
            uint32_t pk[16];
#pragma unroll
            for (int j = 0; j < 16; ++j) {
                pk[j] = f2bf2(wv[2 * j], wv[2 * j + 1]);
                if (term == 0) {
                    wv[2 * j]     -= bflo(pk[j]);
                    wv[2 * j + 1] -= bfhi(pk[j]);
                }
            }
            uint32_t* dst = Wt + term * (NEXP * WST) + e * WST + (tid & 3) * 16;
#pragma unroll
            for (int u = 0; u < 4; ++u)
                *reinterpret_cast<uint4*>(dst + 4 * u) =
                    make_uint4(pk[4 * u], pk[4 * u + 1], pk[4 * u + 2], pk[4 * u + 3]);
        }
    }
    if (tid < NEXP) cntS[tid] = 0;
    asm volatile("cp.async.wait_group 0;" ::: "memory");
    __syncthreads();

    // ---- GEMM: warp wid owns rows [wid*16, wid*16+16), full n=64 (8 n-tiles) ----
    const int g  = lane >> 2;
    const int tg = lane & 3;
    const int m0 = wid * 16;

    float accM[8][4];
#pragma unroll
    for (int t = 0; t < 8; ++t)
#pragma unroll
        for (int i = 0; i < 4; ++i) accM[t][i] = 0.f;

    const float* xr0 = xs + (m0 + g) * XST + tg * 2;
    const float* xr1 = xs + (m0 + g + 8) * XST + tg * 2;
    const uint32_t* WtB = Wt + g * WST;     // row g within n-tile

#pragma unroll
    for (int s = 0; s < 8; ++s) {
        const int c = 16 * s;
        float2 x00 = *reinterpret_cast<const float2*>(xr0 + c);
        float2 x01 = *reinterpret_cast<const float2*>(xr0 + c + 8);
        float2 x10 = *reinterpret_cast<const float2*>(xr1 + c);
        float2 x11 = *reinterpret_cast<const float2*>(xr1 + c + 8);

        uint32_t A0[4], A1[4];
        A0[0] = f2bf2(x00.x, x00.y); A0[1] = f2bf2(x10.x, x10.y);
        A0[2] = f2bf2(x01.x, x01.y); A0[3] = f2bf2(x11.x, x11.y);
        x00.x -= bflo(A0[0]); x00.y -= bfhi(A0[0]);
        x10.x -= bflo(A0[1]); x10.y -= bfhi(A0[1]);
        x01.x -= bflo(A0[2]); x01.y -= bfhi(A0[2]);
        x11.x -= bflo(A0[3]); x11.y -= bfhi(A0[3]);
        A1[0] = f2bf2(x00.x, x00.y); A1[1] = f2bf2(x10.x, x10.y);
        A1[2] = f2bf2(x01.x, x01.y); A1[3] = f2bf2(x11.x, x11.y);

        const int bp = 8 * s + tg;
#pragma unroll
        for (int t = 0; t < 8; ++t) {
            const uint32_t* r0 = WtB + (8 * t) * WST + bp;
            uint32_t B00 = r0[0],            B01 = r0[4];              // term0
            uint32_t B10 = r0[NEXP * WST],   B11 = r0[NEXP * WST + 4]; // term1
            float tm[4], tc[4];
            mma_zc(tm, A0, B00, B01);            // main a0*b0
            mma_zc(tc, A0, B10, B11);            // a0*b1
            mma16816(tc, A1, B00, B01);          // + a1*b0
            mma16816(tc, A1, B10, B11);          // + a1*b1
            accM[t][0] += tm[0] + tc[0];
            accM[t][1] += tm[1] + tc[1];
            accM[t][2] += tm[2] + tc[2];
            accM[t][3] += tm[3] + tc[3];
        }
    }
    __syncthreads();   // all xs/Wt reads done; safe to overlay L

    // ---- scatter logits to L[token][expert] ----
#pragma unroll
    for (int t = 0; t < 8; ++t) {
        int col = 8 * t + tg * 2;
        *reinterpret_cast<float2*>(L + (m0 + g) * LST + col)     = make_float2(accM[t][0], accM[t][1]);
        *reinterpret_cast<float2*>(L + (m0 + g + 8) * LST + col) = make_float2(accM[t][2], accM[t][3]);
    }
    __syncthreads();

    // ---- per-token top-6 / softmax / outputs (threads 0..127) ----
    if (tid < TBK) {
        const int t = tid;
        const int lw = tid & 31;
        const int wE = tid >> 5;
        float v[64];
#pragma unroll
        for (int j = 0; j < 16; ++j) {
            float4 q = *reinterpret_cast<const float4*>(L + t * LST + 4 * j);
            v[4 * j] = q.x; v[4 * j + 1] = q.y; v[4 * j + 2] = q.z; v[4 * j + 3] = q.w;
        }

        // top-7 to measure boundary gaps
        unsigned long long mask = 0ull;
        float tv[7]; int ti[7];
#pragma unroll
        for (int p = 0; p < 7; ++p) {
            ti[p] = find_top(v, mask, tv[p]);
            mask |= 1ull << ti[p];
        }
        bool flg = false;
#pragma unroll
        for (int p = 0; p < 6; ++p) flg |= (tv[p] - tv[p + 1]) < 2e-5f;

        // near-tie tokens: warp-cooperative exact fp32 recompute (rare)
        unsigned fmsk = __ballot_sync(0xffffffffu, flg);
        float* rs = rescr + wE * 64;
        while (fmsk) {
            int src = __ffs(fmsk) - 1;
            fmsk &= fmsk - 1;
            long long gtok = blk * TBK + wE * 32 + src;
            const float* xrow = x + gtok * HID;
            const float* w0 = W + (2 * lw) * HID;
            float a0 = 0.f, a1 = 0.f;
#pragma unroll 8
            for (int k = 0; k < HID; ++k) {
                float xv = __ldg(xrow + k);
                a0 = fmaf(xv, __ldg(w0 + k), a0);
                a1 = fmaf(xv, __ldg(w0 + HID + k), a1);
            }
            rs[2 * lw] = a0;
            rs[2 * lw + 1] = a1;
            __syncwarp();
            if (lw == src) {
#pragma unroll
                for (int i = 0; i < 64; ++i) v[i] = rs[i];
            }
            __syncwarp();
        }
        if (flg) {
            mask = 0ull;
#pragma unroll
            for (int p = 0; p < 6; ++p) {
                ti[p] = find_top(v, mask, tv[p]);
                mask |= 1ull << ti[p];
            }
        }

        float m1 = tv[0];
        float Z = 0.f;
#pragma unroll
        for (int j = 0; j < 16; ++j) {
            float e0 = __expf(v[4 * j]     - m1);
            float e1 = __expf(v[4 * j + 1] - m1);
            float e2 = __expf(v[4 * j + 2] - m1);
            float e3 = __expf(v[4 * j + 3] - m1);
            Z += (e0 + e1) + (e2 + e3);
            *reinterpret_cast<float4*>(L + t * LST + 4 * j) = make_float4(e0, e1, e2, e3);
        }
        zinv[t] = 1.f / Z;

        float ev[6]; float E6 = 0.f;
#pragma unroll
        for (int p = 0; p < 6; ++p) { ev[p] = __expf(tv[p] - m1); E6 += ev[p]; }
        float invd = 1.f / (E6 + 1e-20f * Z);   // == ref renormalization exactly

        size_t gt = (size_t)blk * TBK + t;
        float* oi = out + gt * 6;
        float* ow = out + (size_t)N * 6 + gt * 6;
#pragma unroll
        for (int p = 0; p < 6; ++p) {
            oi[p] = (float)ti[p];
            ow[p] = ev[p] * invd;
            atomicAdd(&cntS[ti[p]], 1);
        }
    }
    __syncthreads();

    // ---- Pi column sums (part overlays Wt — Wt reads finished) ----
    {
        int e = tid & 63;
        int q = tid >> 6;
        float s0 = 0.f, s1 = 0.f;
#pragma unroll
        for (int j = 0; j < 32; j += 2) {
            int t0 = q * 32 + j;
            s0 = fmaf(L[(t0 + 0) * LST + e], zinv[t0 + 0], s0);
            s1 = fmaf(L[(t0 + 1) * LST + e], zinv[t0 + 1], s1);
        }
        part[q * 64 + e] = s0 + s1;
    }
    __syncthreads();

    if (tid < NEXP) {
        float s = ((part[tid] + part[64 + tid]) + (part[128 + tid] + part[192 + tid]));
        atomicAdd(&g_scoreFix[tid], (unsigned long long)(s * 1073741824.0f)); // *2^30
        atomicAdd(&g_cnt[tid], cntS[tid]);
    }
    __syncthreads();

    // ---- last-block finalize: aux loss + accumulator self-reset ----
    if (tid == 0) {
        __threadfence();
        int r = atomicAdd(&g_sync, 1);
        lastF[0] = (r == (int)gridDim.x - 1) ? 1 : 0;
    }
    __syncthreads();
    if (lastF[0]) {
        __threadfence();
        if (tid < NEXP) {
            double invN = 1.0 / (double)N;
            double Pi = (double)g_scoreFix[tid] * (1.0 / 1073741824.0) * invN;
            double fi = (double)g_cnt[tid] * 64.0 / ((double)N * 6.0);
            dterm[tid] = Pi * fi;
            g_scoreFix[tid] = 0ull;
            g_cnt[tid]      = 0;
        }
        __syncthreads();
        if (tid == 0) {
            double aux = 0.0;
            for (int e = 0; e < NEXP; ++e) aux += dterm[e];
            out[(size_t)N * 12] = (float)(aux * 1e-3);
            g_sync = 0;
        }
    }
}

extern "C" void kernel_launch(void* const* d_in, const int* in_sizes, int n_in,
                              void* d_out, int out_size) {
    const float* x = (const float*)d_in[0];
    const float* W = (const float*)d_in[1];
    int N = in_sizes[0] / HID;

    int smem_bytes = SW_TOTAL * (int)sizeof(float) + 128;
    cudaFuncSetAttribute(moe_main, cudaFuncAttributeMaxDynamicSharedMemorySize, smem_bytes);
    moe_main<<<N / TBK, NTH, smem_bytes>>>(x, W, (float*)d_out, N);
}

// round 15
// speedup vs baseline: 1.4866x; 1.0872x over previous
#include <cuda_runtime.h>
#include <cstdint>

#define TBK   128
#define NTH   256
#define HID   128
#define NEXP  64
#define WST   68        // Wt row stride (u32 words)
#define LST   68        // logits row stride (fp32 words)
#define NEGINF (__int_as_float(0xff800000u))

// ---- smem word offsets ----
#define SW_L     0                    // fp32 [128][68] logits -> exps
#define SW_WT    8704                 // u32  2 x [64][68] bf16-pair terms
#define SW_ZINV  17408                // fp32 [128]
#define SW_CNT   17536                // int  [64]
#define SW_LASTF 17600                // int
#define SW_RS    17604                // fp32 [8][64] recompute scratch (per warp)
#define SW_TOTAL 18116
#define SW_PART  8704                 // overlay on Wt: fp32 [4][64]
#define SW_DTERM 9216                 // overlay on Wt: double[64] (byte 36864)

__device__ unsigned long long g_scoreFix[NEXP];
__device__ int g_cnt[NEXP];
__device__ int g_sync;

// pack two fp32 -> bf16x2 {lo, hi}; PTX cvt packs first src into HIGH half
__device__ __forceinline__ uint32_t f2bf2(float lo, float hi) {
    uint32_t r;
    asm("cvt.rn.bf16x2.f32 %0, %1, %2;" : "=r"(r) : "f"(hi), "f"(lo));
    return r;
}
__device__ __forceinline__ float bflo(uint32_t p) { return __uint_as_float(p << 16); }
__device__ __forceinline__ float bfhi(uint32_t p) { return __uint_as_float(p & 0xFFFF0000u); }

// C-in chained accumulate (small corrections only)
__device__ __forceinline__ void mma16816(float* d, const uint32_t* a, uint32_t b0, uint32_t b1) {
    asm volatile(
        "mma.sync.aligned.m16n8k16.row.col.f32.bf16.bf16.f32 "
        "{%0,%1,%2,%3}, {%4,%5,%6,%7}, {%8,%9}, {%0,%1,%2,%3};"
        : "+f"(d[0]), "+f"(d[1]), "+f"(d[2]), "+f"(d[3])
        : "r"(a[0]), "r"(a[1]), "r"(a[2]), "r"(a[3]), "r"(b0), "r"(b1));
}
// zero-C MMA: no cross-MMA truncation compounding at logit magnitude
__device__ __forceinline__ void mma_zc(float* d, const uint32_t* a, uint32_t b0, uint32_t b1) {
    asm volatile(
        "mma.sync.aligned.m16n8k16.row.col.f32.bf16.bf16.f32 "
        "{%0,%1,%2,%3}, {%4,%5,%6,%7}, {%8,%9}, {%10,%10,%10,%10};"
        : "=f"(d[0]), "=f"(d[1]), "=f"(d[2]), "=f"(d[3])
        : "r"(a[0]), "r"(a[1]), "r"(a[2]), "r"(a[3]), "r"(b0), "r"(b1), "f"(0.f));
}

// masked argmax over 32 register floats; exact lower-index tie-break
__device__ __forceinline__ int find_top32(const float (&v)[32], unsigned mask, float& mval) {
    float w[16];
#pragma unroll
    for (int i = 0; i < 16; ++i) {
        float x0 = ((mask >> (2 * i)) & 1u)     ? NEGINF : v[2 * i];
        float x1 = ((mask >> (2 * i + 1)) & 1u) ? NEGINF : v[2 * i + 1];
        w[i] = fmaxf(x0, x1);
    }
#pragma unroll
    for (int n = 8; n >= 1; n >>= 1)
#pragma unroll
        for (int i = 0; i < n; ++i) w[i] = fmaxf(w[2 * i], w[2 * i + 1]);
    float m = w[0];
    int b0 = 32, b1 = 32;
#pragma unroll
    for (int i = 15; i >= 0; --i) {
        float y0 = ((mask >> i) & 1u) ? NEGINF : v[i];
        if (y0 == m) b0 = i;
        float y1 = ((mask >> (i + 16)) & 1u) ? NEGINF : v[i + 16];
        if (y1 == m) b1 = i + 16;
    }
    mval = m;
    return (b0 < 32) ? b0 : b1;
}

// local top-7 + pair-exchange + merge. h = expert half (0: 0-31, 1: 32-63).
// Produces identical global top-7 (desc, exact lower-index tie-break) on both pair lanes.
__device__ __forceinline__ void select_top7(const float (&v)[32], int h,
                                            float (&tv)[7], int (&ti)[7]) {
    unsigned mask = 0;
    float lv[7]; int li[7];
#pragma unroll
    for (int p = 0; p < 7; ++p) {
        li[p] = find_top32(v, mask, lv[p]);
        mask |= 1u << li[p];
        li[p] += h * 32;               // globalize
    }
    float ov[7]; int oi[7];
#pragma unroll
    for (int p = 0; p < 7; ++p) {
        ov[p] = __shfl_xor_sync(0xffffffffu, lv[p], 1);
        oi[p] = __shfl_xor_sync(0xffffffffu, li[p], 1);
    }
    float av[7], bv[7]; int ai[7], bi[7];
#pragma unroll
    for (int p = 0; p < 7; ++p) {       // a = low-expert half, b = high half
        av[p] = h ? ov[p] : lv[p];  ai[p] = h ? oi[p] : li[p];
        bv[p] = h ? lv[p] : ov[p];  bi[p] = h ? li[p] : oi[p];
    }
#pragma unroll
    for (int p = 0; p < 7; ++p) {
        bool ta = av[0] >= bv[0];       // tie -> low half = lower expert idx
        tv[p] = ta ? av[0] : bv[0];
        ti[p] = ta ? ai[0] : bi[0];
        if (ta) {
            av[0]=av[1]; av[1]=av[2]; av[2]=av[3]; av[3]=av[4]; av[4]=av[5]; av[5]=av[6]; av[6]=NEGINF;
            ai[0]=ai[1]; ai[1]=ai[2]; ai[2]=ai[3]; ai[3]=ai[4]; ai[4]=ai[5]; ai[5]=ai[6];
        } else {
            bv[0]=bv[1]; bv[1]=bv[2]; bv[2]=bv[3]; bv[3]=bv[4]; bv[4]=bv[5]; bv[5]=bv[6]; bv[6]=NEGINF;
            bi[0]=bi[1]; bi[1]=bi[2]; bi[2]=bi[3]; bi[3]=bi[4]; bi[4]=bi[5]; bi[5]=bi[6];
        }
    }
}

extern __shared__ float smf[];

__global__ __launch_bounds__(NTH, 3)
void moe_main(const float* __restrict__ x, const float* __restrict__ W,
              float* __restrict__ out, int N) {
    const int tid  = threadIdx.x;
    const int wid  = tid >> 5;
    const int lane = tid & 31;
    const long long blk = blockIdx.x;

    float*    L     = smf + SW_L;
    uint32_t* Wt    = reinterpret_cast<uint32_t*>(smf + SW_WT);
    float*    zinv  = smf + SW_ZINV;
    int*      cntS  = reinterpret_cast<int*>(smf + SW_CNT);
    int*      lastF = reinterpret_cast<int*>(smf + SW_LASTF);
    float*    rescr = smf + SW_RS;
    float*    part  = smf + SW_PART;     // overlay on Wt
    double*   dterm = reinterpret_cast<double*>(smf + SW_DTERM);

    // ---- stage W: 2 bf16-pair terms (thread: e=tid>>2, 32 k vals) ----
    {
        int e  = tid >> 2;
        int kq = (tid & 3) * 32;
        float wv[32];
        const float4* gw = reinterpret_cast<const float4*>(W + e * HID + kq);
#pragma unroll
        for (int j = 0; j < 8; ++j) {
            float4 g = gw[j];
            wv[4 * j] = g.x; wv[4 * j + 1] = g.y; wv[4 * j + 2] = g.z; wv[4 * j + 3] = g.w;
        }
#pragma unroll
        for (int term = 0; term < 2; ++term) {
            uint32_t pk[16];
#pragma unroll
            for (int j = 0; j < 16; ++j) {
                pk[j] = f2bf2(wv[2 * j], wv[2 * j + 1]);
                if (term == 0) {
                    wv[2 * j]     -= bflo(pk[j]);
                    wv[2 * j + 1] -= bfhi(pk[j]);
                }
            }
            uint32_t* dst = Wt + term * (NEXP * WST) + e * WST + (tid & 3) * 16;
#pragma unroll
            for (int u = 0; u < 4; ++u)
                *reinterpret_cast<uint4*>(dst + 4 * u) =
                    make_uint4(pk[4 * u], pk[4 * u + 1], pk[4 * u + 2], pk[4 * u + 3]);
        }
    }
    if (tid < NEXP) cntS[tid] = 0;
    __syncthreads();

    // ---- GEMM: warp wid owns rows [wid*16, +16), all 64 experts (8 n-tiles).
    //      A fragments straight from gmem (per-warp-exclusive rows; 100% sector use).
    const int g  = lane >> 2;
    const int tg = lane & 3;
    const int m0 = wid * 16;

    float accM[8][4];
#pragma unroll
    for (int t = 0; t < 8; ++t)
#pragma unroll
        for (int i = 0; i < 4; ++i) accM[t][i] = 0.f;

    const float* gx0 = x + blk * (long long)(TBK * HID) + (m0 + g) * HID + tg * 2;
    const float* gx1 = gx0 + 8 * HID;
    const uint32_t* WtB = Wt + g * WST;

#pragma unroll
    for (int s = 0; s < 8; ++s) {
        const int c = 16 * s;
        float2 x00 = *reinterpret_cast<const float2*>(gx0 + c);
        float2 x01 = *reinterpret_cast<const float2*>(gx0 + c + 8);
        float2 x10 = *reinterpret_cast<const float2*>(gx1 + c);
        float2 x11 = *reinterpret_cast<const float2*>(gx1 + c + 8);

        uint32_t A0[4], A1[4];
        A0[0] = f2bf2(x00.x, x00.y); A0[1] = f2bf2(x10.x, x10.y);
        A0[2] = f2bf2(x01.x, x01.y); A0[3] = f2bf2(x11.x, x11.y);
        x00.x -= bflo(A0[0]); x00.y -= bfhi(A0[0]);
        x10.x -= bflo(A0[1]); x10.y -= bfhi(A0[1]);
        x01.x -= bflo(A0[2]); x01.y -= bfhi(A0[2]);
        x11.x -= bflo(A0[3]); x11.y -= bfhi(A0[3]);
        A1[0] = f2bf2(x00.x, x00.y); A1[1] = f2bf2(x10.x, x10.y);
        A1[2] = f2bf2(x01.x, x01.y); A1[3] = f2bf2(x11.x, x11.y);

        const int bp = 8 * s + tg;
#pragma unroll
        for (int t = 0; t < 8; ++t) {
            const uint32_t* r0 = WtB + (8 * t) * WST + bp;
            uint32_t B00 = r0[0],          B01 = r0[4];
            uint32_t B10 = r0[NEXP * WST], B11 = r0[NEXP * WST + 4];
            float tm[4], tc[4];
            mma_zc(tm, A0, B00, B01);            // main a0*b0 (zero-C)
            mma_zc(tc, A0, B10, B11);            // a0*b1
            mma16816(tc, A1, B00, B01);          // + a1*b0
            mma16816(tc, A1, B10, B11);          // + a1*b1
            accM[t][0] += tm[0] + tc[0];
            accM[t][1] += tm[1] + tc[1];
            accM[t][2] += tm[2] + tc[2];
            accM[t][3] += tm[3] + tc[3];
        }
    }

    // ---- scatter logits to L[token][expert] (dedicated region, no WAR) ----
#pragma unroll
    for (int t = 0; t < 8; ++t) {
        int col = 8 * t + tg * 2;
        *reinterpret_cast<float2*>(L + (m0 + g) * LST + col)     = make_float2(accM[t][0], accM[t][1]);
        *reinterpret_cast<float2*>(L + (m0 + g + 8) * LST + col) = make_float2(accM[t][2], accM[t][3]);
    }
    __syncthreads();

    // ---- epilogue: 2 threads/token; all 256 threads busy ----
    {
        const int t = tid >> 1;            // token
        const int h = tid & 1;             // expert half
        const int warpE = wid;             // warp handles 16 tokens

        float v[32];
#pragma unroll
        for (int j = 0; j < 8; ++j) {
            float4 q = *reinterpret_cast<const float4*>(L + t * LST + h * 32 + 4 * j);
            v[4 * j] = q.x; v[4 * j + 1] = q.y; v[4 * j + 2] = q.z; v[4 * j + 3] = q.w;
        }

        float tv[7]; int ti[7];
        select_top7(v, h, tv, ti);

        bool flg = false;
#pragma unroll
        for (int p = 0; p < 6; ++p) flg |= (tv[p] - tv[p + 1]) < 2e-5f;

        unsigned fmsk = __ballot_sync(0xffffffffu, flg);
        if (fmsk) {
            // warp-cooperative exact fp32 recompute of flagged tokens (rare)
            unsigned em = fmsk & 0x55555555u;
            float* rs = rescr + warpE * 64;
            while (em) {
                int src = __ffs(em) - 1;
                em &= em - 1;
                long long gtok = blk * TBK + warpE * 16 + (src >> 1);
                const float* xrow = x + gtok * HID;
                const float* w0 = W + (2 * lane) * HID;
                float a0 = 0.f, a1 = 0.f;
#pragma unroll 8
                for (int k = 0; k < HID; ++k) {
                    float xv = __ldg(xrow + k);
                    a0 = fmaf(xv, __ldg(w0 + k), a0);
                    a1 = fmaf(xv, __ldg(w0 + HID + k), a1);
                }
                rs[2 * lane] = a0;
                rs[2 * lane + 1] = a1;
                __syncwarp();
                if ((lane >> 1) == (src >> 1)) {
#pragma unroll
                    for (int i = 0; i < 32; ++i) v[i] = rs[h * 32 + i];
                }
                __syncwarp();
            }
            select_top7(v, h, tv, ti);     // whole warp: shuffles stay convergent
        }

        float m1 = tv[0];
        float Zh = 0.f;
#pragma unroll
        for (int j = 0; j < 8; ++j) {
            float e0 = __expf(v[4 * j]     - m1);
            float e1 = __expf(v[4 * j + 1] - m1);
            float e2 = __expf(v[4 * j + 2] - m1);
            float e3 = __expf(v[4 * j + 3] - m1);
            Zh += (e0 + e1) + (e2 + e3);
            *reinterpret_cast<float4*>(L + t * LST + h * 32 + 4 * j) =
                make_float4(e0, e1, e2, e3);
        }
        float Z = Zh + __shfl_xor_sync(0xffffffffu, Zh, 1);

        if (h == 0) {
            zinv[t] = 1.f / Z;
            float ev[6]; float E6 = 0.f;
#pragma unroll
            for (int p = 0; p < 6; ++p) { ev[p] = __expf(tv[p] - m1); E6 += ev[p]; }
            float invd = 1.f / (E6 + 1e-20f * Z);   // == ref renormalization exactly

            size_t gt = (size_t)blk * TBK + t;
            float* oi = out + gt * 6;
            float* ow = out + (size_t)N * 6 + gt * 6;
#pragma unroll
            for (int p = 0; p < 6; ++p) {
                oi[p] = (float)ti[p];
                ow[p] = ev[p] * invd;
                atomicAdd(&cntS[ti[p]], 1);
            }
        }
    }
    __syncthreads();

    // ---- Pi column sums (part overlays Wt — Wt reads finished) ----
    {
        int e = tid & 63;
        int q = tid >> 6;
        float s0 = 0.f, s1 = 0.f;
#pragma unroll
        for (int j = 0; j < 32; j += 2) {
            int t0 = q * 32 + j;
            s0 = fmaf(L[(t0 + 0) * LST + e], zinv[t0 + 0], s0);
            s1 = fmaf(L[(t0 + 1) * LST + e], zinv[t0 + 1], s1);
        }
        part[q * 64 + e] = s0 + s1;
    }
    __syncthreads();

    if (tid < NEXP) {
        float s = ((part[tid] + part[64 + tid]) + (part[128 + tid] + part[192 + tid]));
        atomicAdd(&g_scoreFix[tid], (unsigned long long)(s * 1073741824.0f)); // *2^30
        atomicAdd(&g_cnt[tid], cntS[tid]);
    }
    __syncthreads();

    // ---- last-block finalize: aux loss + accumulator self-reset ----
    if (tid == 0) {
        __threadfence();
        int r = atomicAdd(&g_sync, 1);
        lastF[0] = (r == (int)gridDim.x - 1) ? 1 : 0;
    }
    __syncthreads();
    if (lastF[0]) {
        __threadfence();
        if (tid < NEXP) {
            double invN = 1.0 / (double)N;
            double Pi = (double)g_scoreFix[tid] * (1.0 / 1073741824.0) * invN;
            double fi = (double)g_cnt[tid] * 64.0 / ((double)N * 6.0);
            dterm[tid] = Pi * fi;
            g_scoreFix[tid] = 0ull;
            g_cnt[tid]      = 0;
        }
        __syncthreads();
        if (tid == 0) {
            double aux = 0.0;
            for (int e = 0; e < NEXP; ++e) aux += dterm[e];
            out[(size_t)N * 12] = (float)(aux * 1e-3);
            g_sync = 0;
        }
    }
}

extern "C" void kernel_launch(void* const* d_in, const int* in_sizes, int n_in,
                              void* d_out, int out_size) {
    const float* x = (const float*)d_in[0];
    const float* W = (const float*)d_in[1];
    int N = in_sizes[0] / HID;

    int smem_bytes = SW_TOTAL * (int)sizeof(float) + 128;
    cudaFuncSetAttribute(moe_main, cudaFuncAttributeMaxDynamicSharedMemorySize, smem_bytes);
    moe_main<<<N / TBK, NTH, smem_bytes>>>(x, W, (float*)d_out, N);
}